// round 8
// baseline (speedup 1.0000x reference)
#include <cuda_runtime.h>
#include <cstddef>
#include <cstdint>

// MoEGate, 3-phase: (A) W transpose -> wT[k][e], (B) split-K GEMM with
// f32x2 expert-pair packing -> fp32 partial logits, (C) epilogue
// (merge halves, softmax, top-6 + renorm, seq-aux loss).
// x: [T=16384, h=2048] f32, W: [E=64, h] f32.
// Output (f32): [topk_idx (T*6) | topk_weight (T*6) | aux_loss (1)]
//
// Tile math (per lane): 4 tokens x 4 expert-pairs -> per 4 k-steps:
// 64 FFMA2 vs 12 LDS.128 (48 return-cyc) -> crossbar wall ~1.4x lower
// than FMA wall instead of 2.5x higher (round-7 ncu showed the old
// 8tok x 2exp tile pinned at the LDS-return wall ~150us).

#define NE 64
#define KTOP 6
#define NB 4
#define MAXT 16384
#define MAXH 2048
#define TPB 64                // tokens per GEMM block
#define THREADS 128           // 4 warps; lane = lt*8 + le
#define CHUNK 32              // k per stage
#define XPITCH 36             // floats (144B, 16B-aligned rows)
#define NBLK_C 256            // epilogue blocks = T/TPB
#define BPB 64                // epilogue blocks per batch

__device__ float    g_wt[MAXH * NE];             // W^T [k][e], 512KB
__device__ float    g_logits[2][MAXT * NE];      // split-K partials, 8MB
__device__ float    g_pscore[NBLK_C * NE];
__device__ int      g_pcnt[NBLK_C * NE];
__device__ unsigned g_ticket;                    // self-resetting

static __device__ __forceinline__ void ffma2(unsigned long long& d,
                                             unsigned long long a,
                                             unsigned long long b) {
    asm("fma.rn.f32x2 %0, %1, %2, %0;" : "+l"(d) : "l"(a), "l"(b));
}
static __device__ __forceinline__ void add2(unsigned long long& d,
                                            unsigned long long a) {
    asm("add.rn.f32x2 %0, %0, %1;" : "+l"(d) : "l"(a));
}
static __device__ __forceinline__ unsigned long long dup2(float f) {
    unsigned long long r;
    asm("mov.b64 %0, {%1, %1};" : "=l"(r) : "f"(f));
    return r;
}
static __device__ __forceinline__ void cpa16(uint32_t dst, const void* src) {
    asm volatile("cp.async.cg.shared.global [%0], [%1], 16;"
                 :: "r"(dst), "l"(src));
}

// ---------------- A: transpose W[e][k] -> wT[k][e] ----------------
__global__ void transpose_kernel(const float* __restrict__ w, int h) {
    __shared__ float s[64 * 65];
    const int k0 = blockIdx.x * 64;
    for (int idx = threadIdx.x; idx < 64 * 64; idx += 256) {
        int e = idx >> 6, kk = idx & 63;
        s[kk * 65 + e] = w[(size_t)e * h + k0 + kk];   // coalesced read
    }
    __syncthreads();
    for (int idx = threadIdx.x; idx < 64 * 64; idx += 256) {
        int kk = idx >> 6, e = idx & 63;
        g_wt[(size_t)(k0 + kk) * NE + e] = s[kk * 65 + e];  // coalesced write
    }
}

// ---------------- B: split-K GEMM -> partial logits ----------------
__global__ __launch_bounds__(THREADS, 4) void gemm_kernel(
    const float* __restrict__ x, int h)
{
    __shared__ __align__(16) float xs[2][TPB * XPITCH];
    __shared__ __align__(16) float wts[2][CHUNK * NE];

    const int tid  = threadIdx.x;
    const int lane = tid & 31;
    const int warp = tid >> 5;
    const int lt   = lane >> 3;       // token group 0..3
    const int le   = lane & 7;        // expert group 0..7
    const int tile = blockIdx.x >> 1;
    const int kh   = blockIdx.x & 1;  // k-half
    const int tok0 = tile * TPB;
    const int kbase = kh * (h >> 1);
    const int nchunk = (h >> 1) / CHUNK;   // 32

    unsigned long long acc[4][4], sum[4][4];
#pragma unroll
    for (int j = 0; j < 4; j++)
#pragma unroll
        for (int p = 0; p < 4; p++) { acc[j][p] = 0ull; sum[j][p] = 0ull; }

    // stage: x 64 rows x 8 quads (512) + wT 32 rows x 16 quads (512)
    auto stage = [&](int c, int buf) {
        const int k0 = kbase + c * CHUNK;
#pragma unroll
        for (int j = 0; j < 8; j++) {
            int cj = tid + j * THREADS;
            if (cj < 512) {
                int row = cj >> 3, q = cj & 7;
                cpa16((uint32_t)__cvta_generic_to_shared(
                          &xs[buf][row * XPITCH + q * 4]),
                      x + (size_t)(tok0 + row) * h + k0 + q * 4);
            } else {
                int c2 = cj - 512;
                int k = c2 >> 4, q = c2 & 15;
                cpa16((uint32_t)__cvta_generic_to_shared(
                          &wts[buf][k * NE + q * 4]),
                      g_wt + (size_t)(k0 + k) * NE + q * 4);
            }
        }
    };

    stage(0, 0);
    asm volatile("cp.async.commit_group;" ::: "memory");

    for (int c = 0; c < nchunk; c++) {
        const int buf = c & 1;
        asm volatile("cp.async.wait_group 0;" ::: "memory");
        __syncthreads();
        if (c + 1 < nchunk) {
            stage(c + 1, buf ^ 1);
            asm volatile("cp.async.commit_group;" ::: "memory");
        }

        const float* xb = &xs[buf][(warp * 16 + lt * 4) * XPITCH];
        const float* wb = &wts[buf][le * 8];
#pragma unroll
        for (int kk = 0; kk < CHUNK; kk += 4) {
            float4 xv0 = *(const float4*)(xb + 0 * XPITCH + kk);
            float4 xv1 = *(const float4*)(xb + 1 * XPITCH + kk);
            float4 xv2 = *(const float4*)(xb + 2 * XPITCH + kk);
            float4 xv3 = *(const float4*)(xb + 3 * XPITCH + kk);
#pragma unroll
            for (int k2 = 0; k2 < 4; k2++) {
                ulonglong2 wlo = *(const ulonglong2*)(wb + (kk + k2) * NE);
                ulonglong2 whi = *(const ulonglong2*)(wb + (kk + k2) * NE + 4);
                unsigned long long d0 = dup2(((const float*)&xv0)[k2]);
                unsigned long long d1 = dup2(((const float*)&xv1)[k2]);
                unsigned long long d2 = dup2(((const float*)&xv2)[k2]);
                unsigned long long d3 = dup2(((const float*)&xv3)[k2]);
                ffma2(acc[0][0], d0, wlo.x); ffma2(acc[0][1], d0, wlo.y);
                ffma2(acc[0][2], d0, whi.x); ffma2(acc[0][3], d0, whi.y);
                ffma2(acc[1][0], d1, wlo.x); ffma2(acc[1][1], d1, wlo.y);
                ffma2(acc[1][2], d1, whi.x); ffma2(acc[1][3], d1, whi.y);
                ffma2(acc[2][0], d2, wlo.x); ffma2(acc[2][1], d2, wlo.y);
                ffma2(acc[2][2], d2, whi.x); ffma2(acc[2][3], d2, whi.y);
                ffma2(acc[3][0], d3, wlo.x); ffma2(acc[3][1], d3, wlo.y);
                ffma2(acc[3][2], d3, whi.x); ffma2(acc[3][3], d3, whi.y);
            }
        }
        // merge 32-term chunk partials (two-level accumulation for accuracy)
#pragma unroll
        for (int j = 0; j < 4; j++)
#pragma unroll
            for (int p = 0; p < 4; p++) { add2(sum[j][p], acc[j][p]); acc[j][p] = 0ull; }
    }

    // store partial logits: lane covers tokens (warp*16+lt*4+j), experts 8le+2p..+1
    float* gl = g_logits[kh];
#pragma unroll
    for (int j = 0; j < 4; j++) {
        int t = tok0 + warp * 16 + lt * 4 + j;
#pragma unroll
        for (int p = 0; p < 4; p++) {
            union { unsigned long long u; float2 f; } cv; cv.u = sum[j][p];
            *(float2*)(gl + (size_t)t * NE + 8 * le + 2 * p) = cv.f;
        }
    }
}

// ---------------- C: epilogue ----------------
__global__ __launch_bounds__(THREADS) void epi_kernel(
    float* __restrict__ out, int T, int S)
{
    __shared__ float score_acc[NE];
    __shared__ int   cnt_acc[NE];
    __shared__ unsigned is_last;
    __shared__ float part[4];

    const int tid  = threadIdx.x;
    const int lane = tid & 31;
    const int warp = tid >> 5;
    const int lt   = lane >> 3;
    const int le   = lane & 7;
    const int bid  = blockIdx.x;
    const int tok0 = bid * TPB;

    if (tid < NE) { score_acc[tid] = 0.0f; cnt_acc[tid] = 0; }
    __syncthreads();

    for (int j = 0; j < 4; j++) {
        const int t = tok0 + warp * 16 + lt * 4 + j;
        // merge split-K halves: 8 experts per lane
        float4 a0 = *(const float4*)(g_logits[0] + (size_t)t * NE + 8 * le);
        float4 a1 = *(const float4*)(g_logits[0] + (size_t)t * NE + 8 * le + 4);
        float4 b0 = *(const float4*)(g_logits[1] + (size_t)t * NE + 8 * le);
        float4 b1 = *(const float4*)(g_logits[1] + (size_t)t * NE + 8 * le + 4);
        float v[8];
        v[0]=a0.x+b0.x; v[1]=a0.y+b0.y; v[2]=a0.z+b0.z; v[3]=a0.w+b0.w;
        v[4]=a1.x+b1.x; v[5]=a1.y+b1.y; v[6]=a1.z+b1.z; v[7]=a1.w+b1.w;

        float m = v[0];
#pragma unroll
        for (int i = 1; i < 8; i++) m = fmaxf(m, v[i]);
#pragma unroll
        for (int off = 1; off < 8; off <<= 1)
            m = fmaxf(m, __shfl_xor_sync(0xffffffffu, m, off));

        float s[8], z = 0.0f;
#pragma unroll
        for (int i = 0; i < 8; i++) { s[i] = __expf(v[i] - m); z += s[i]; }
#pragma unroll
        for (int off = 1; off < 8; off <<= 1)
            z += __shfl_xor_sync(0xffffffffu, z, off);
        float inv = 1.0f / z;
#pragma unroll
        for (int i = 0; i < 8; i++) {
            s[i] *= inv;
            atomicAdd(&score_acc[8 * le + i], s[i]);
        }

        // top-6 on logits, stable lowest-index ties
        unsigned used = 0;
        float wsum = 0.0f;
        float outw[KTOP]; int outi[KTOP];
#pragma unroll
        for (int it = 0; it < KTOP; it++) {
            float bv = -3.4e38f; int bi = 127;
#pragma unroll
            for (int i = 0; i < 8; i++) {
                bool ok = !((used >> i) & 1u) && (v[i] > bv);
                bv = ok ? v[i] : bv;
                bi = ok ? (8 * le + i) : bi;
            }
#pragma unroll
            for (int off = 1; off < 8; off <<= 1) {
                float ov = __shfl_xor_sync(0xffffffffu, bv, off);
                int   oi = __shfl_xor_sync(0xffffffffu, bi, off);
                if (ov > bv || (ov == bv && oi < bi)) { bv = ov; bi = oi; }
            }
            // fetch winner's softmax score: owner lane = lt*8 + (bi>>3)
            int ii = bi & 7;
            float cand = s[0];
#pragma unroll
            for (int i = 1; i < 8; i++) cand = (ii == i) ? s[i] : cand;
            float sc = __shfl_sync(0xffffffffu, cand, (lane & 24) | (bi >> 3));
            wsum += sc;
            outw[it] = sc; outi[it] = bi;
            if ((bi >> 3) == le) used |= 1u << (bi & 7);
            if (le == 0) atomicAdd(&cnt_acc[bi], 1);
        }
        if (le == 0) {
            float invw = 1.0f / (wsum + 1e-20f);
#pragma unroll
            for (int it = 0; it < KTOP; it++) {
                out[(size_t)t * KTOP + it] = (float)outi[it];
                out[(size_t)T * KTOP + (size_t)t * KTOP + it] = outw[it] * invw;
            }
        }
    }
    __syncthreads();

    if (tid < NE) {
        g_pscore[bid * NE + tid] = score_acc[tid];
        g_pcnt[bid * NE + tid]   = cnt_acc[tid];
    }
    __threadfence();
    __syncthreads();
    if (tid == 0) {
        unsigned tkt = atomicAdd(&g_ticket, 1u);
        is_last = (tkt == (unsigned)(gridDim.x - 1));
    }
    __syncthreads();

    if (is_last) {
        if (tid == 0) g_ticket = 0;
        __threadfence();
        float local = 0.0f;
        for (int p = tid; p < NB * NE; p += THREADS) {
            int b = p >> 6, e = p & 63;
            float sc = 0.0f; int cn = 0;
            const int base = b * BPB;
            for (int blk = 0; blk < BPB; blk++) {
                sc += g_pscore[(base + blk) * NE + e];
                cn += g_pcnt[(base + blk) * NE + e];
            }
            float ce = (float)cn * ((float)NE / ((float)S * (float)KTOP));
            local += ce * (sc / (float)S);
        }
#pragma unroll
        for (int off = 16; off; off >>= 1)
            local += __shfl_xor_sync(0xffffffffu, local, off);
        if (lane == 0) part[warp] = local;
        __syncthreads();
        if (tid == 0) {
            float sm = part[0] + part[1] + part[2] + part[3];
            out[(size_t)2 * T * KTOP] = (sm / (float)NB) * 1e-3f;
        }
    }
}

extern "C" void kernel_launch(void* const* d_in, const int* in_sizes, int n_in,
                              void* d_out, int out_size) {
    const float* x = (const float*)d_in[0];
    const float* w = (const float*)d_in[1];
    float* out = (float*)d_out;
    int h = in_sizes[1] / NE;     // 2048
    int T = in_sizes[0] / h;      // 16384
    int S = T / NB;               // 4096

    transpose_kernel<<<h / 64, 256>>>(w, h);
    gemm_kernel<<<(T / TPB) * 2, THREADS>>>(x, h);
    epi_kernel<<<T / TPB, THREADS>>>(out, T, S);
}

// round 9
// speedup vs baseline: 1.7783x; 1.7783x over previous
#include <cuda_runtime.h>
#include <cstddef>
#include <cstdint>

// MoEGate, 3-phase: (A) W transpose+permute -> wT[k][perm(e)],
// (B) split-K GEMM, f32x2 expert-pair packing -> fp32 partial logits,
// (C) epilogue (merge halves, softmax, top-6 + renorm, seq-aux loss).
// x: [T=16384, h=2048] f32, W: [E=64, h] f32.
// Output (f32): [topk_idx (T*6) | topk_weight (T*6) | aux_loss (1)]
//
// R8 gave idx-EXACT results (rel_err 2.9e-7) but spilled: 128 regs of
// accumulators under (128,4). R9 keeps the identical summation structure
// (sequential k within 32-chunks, chunk merge, split-K halves) with a
// 2tok x 4pair tile (32 acc regs) and a permuted wT row so both w-LDS.128
// are single-wavefront. Occupancy-driven: ~6 blocks/SM.

#define NE 64
#define KTOP 6
#define NB 4
#define MAXT 16384
#define MAXH 2048
#define TPB 32                // tokens per GEMM block
#define THREADS 128           // 4 warps; lane = lt*8 + le
#define CHUNK 32              // k per stage
#define XPITCH 36             // floats per staged x row
#define EPB 64                // epilogue tokens per block
#define NBLK_C 256            // epilogue blocks = T/EPB
#define BPB 64                // epilogue blocks per batch

__device__ float    g_wt[MAXH * NE];             // wT[k][perm(e)], 512KB
__device__ float    g_logits[2][MAXT * NE];      // split-K partials, 8MB
__device__ float    g_pscore[NBLK_C * NE];
__device__ int      g_pcnt[NBLK_C * NE];
__device__ unsigned g_ticket;                    // self-resetting

static __device__ __forceinline__ void ffma2(unsigned long long& d,
                                             unsigned long long a,
                                             unsigned long long b) {
    asm("fma.rn.f32x2 %0, %1, %2, %0;" : "+l"(d) : "l"(a), "l"(b));
}
static __device__ __forceinline__ void add2(unsigned long long& d,
                                            unsigned long long a) {
    asm("add.rn.f32x2 %0, %0, %1;" : "+l"(d) : "l"(a));
}
static __device__ __forceinline__ unsigned long long dup2(float f) {
    unsigned long long r;
    asm("mov.b64 %0, {%1, %1};" : "=l"(r) : "f"(f));
    return r;
}
static __device__ __forceinline__ void cpa16(uint32_t dst, const void* src) {
    asm volatile("cp.async.cg.shared.global [%0], [%1], 16;"
                 :: "r"(dst), "l"(src));
}

// ---------------- A: transpose W[e][k] -> wT[k][perm(e)] ----------------
// perm(e): e = 8*le + i  ->  (i&4)*8 + le*4 + (i&3)
// so lanes' wlo (experts 8le..8le+3) occupy bytes [le*16, le*16+16) of the
// first 128B half, whi the second half -> conflict-free LDS.128.
__global__ void transpose_kernel(const float* __restrict__ w, int h) {
    __shared__ float s[16 * 65];
    const int k0 = blockIdx.x * 16;
    for (int idx = threadIdx.x; idx < 16 * 64; idx += 256) {
        int e = idx >> 4, kk = idx & 15;
        s[kk * 65 + e] = w[(size_t)e * h + k0 + kk];
    }
    __syncthreads();
    for (int idx = threadIdx.x; idx < 16 * 64; idx += 256) {
        int kk = idx >> 6, e = idx & 63;
        int le = e >> 3, i = e & 7;
        int pos = ((i & 4) << 3) + le * 4 + (i & 3);
        g_wt[(size_t)(k0 + kk) * NE + pos] = s[kk * 65 + e];
    }
}

// ---------------- B: split-K GEMM -> partial logits ----------------
__global__ __launch_bounds__(THREADS) void gemm_kernel(
    const float* __restrict__ x, int h)
{
    __shared__ __align__(16) float xs[2][TPB * XPITCH];
    __shared__ __align__(16) float wts[2][CHUNK * NE];

    const int tid  = threadIdx.x;
    const int lane = tid & 31;
    const int warp = tid >> 5;
    const int lt   = lane >> 3;       // token group 0..3
    const int le   = lane & 7;        // expert group 0..7
    const int tile = blockIdx.x >> 1;
    const int kh   = blockIdx.x & 1;  // k-half
    const int tok0 = tile * TPB;
    const int kbase = kh * (h >> 1);
    const int nchunk = (h >> 1) / CHUNK;   // 32

    unsigned long long acc[2][4], sum[2][4];
#pragma unroll
    for (int j = 0; j < 2; j++)
#pragma unroll
        for (int p = 0; p < 4; p++) { acc[j][p] = 0ull; sum[j][p] = 0ull; }

    // stage: x 32 rows x 8 quads (256) + wT 32 rows x 16 quads (512)
    auto stage = [&](int c, int buf) {
        const int k0 = kbase + c * CHUNK;
#pragma unroll
        for (int j = 0; j < 6; j++) {
            int cj = tid + j * THREADS;
            if (cj < 256) {
                int row = cj >> 3, q = cj & 7;
                cpa16((uint32_t)__cvta_generic_to_shared(
                          &xs[buf][row * XPITCH + q * 4]),
                      x + (size_t)(tok0 + row) * h + k0 + q * 4);
            } else {
                int c2 = cj - 256;
                int k = c2 >> 4, q = c2 & 15;
                cpa16((uint32_t)__cvta_generic_to_shared(
                          &wts[buf][k * NE + q * 4]),
                      g_wt + (size_t)(k0 + k) * NE + q * 4);
            }
        }
    };

    stage(0, 0);
    asm volatile("cp.async.commit_group;" ::: "memory");

    for (int c = 0; c < nchunk; c++) {
        const int buf = c & 1;
        asm volatile("cp.async.wait_group 0;" ::: "memory");
        __syncthreads();
        if (c + 1 < nchunk) {
            stage(c + 1, buf ^ 1);
            asm volatile("cp.async.commit_group;" ::: "memory");
        }

        const float* xb = &xs[buf][(warp * 8 + lt * 2) * XPITCH];
        const float* wb = &wts[buf][le * 4];   // wlo at +0, whi at +32
#pragma unroll
        for (int kk = 0; kk < CHUNK; kk += 4) {
            float4 xv0 = *(const float4*)(xb + 0 * XPITCH + kk);
            float4 xv1 = *(const float4*)(xb + 1 * XPITCH + kk);
#pragma unroll
            for (int k2 = 0; k2 < 4; k2++) {
                ulonglong2 wlo = *(const ulonglong2*)(wb + (kk + k2) * NE);
                ulonglong2 whi = *(const ulonglong2*)(wb + (kk + k2) * NE + 32);
                unsigned long long d0 = dup2(((const float*)&xv0)[k2]);
                unsigned long long d1 = dup2(((const float*)&xv1)[k2]);
                ffma2(acc[0][0], d0, wlo.x); ffma2(acc[0][1], d0, wlo.y);
                ffma2(acc[0][2], d0, whi.x); ffma2(acc[0][3], d0, whi.y);
                ffma2(acc[1][0], d1, wlo.x); ffma2(acc[1][1], d1, wlo.y);
                ffma2(acc[1][2], d1, whi.x); ffma2(acc[1][3], d1, whi.y);
            }
        }
        // merge 32-term chunk partials (same structure as R8 -> same bits)
#pragma unroll
        for (int j = 0; j < 2; j++)
#pragma unroll
            for (int p = 0; p < 4; p++) { add2(sum[j][p], acc[j][p]); acc[j][p] = 0ull; }
    }

    // store partial logits [t][e]: lane -> tokens warp*8+lt*2+{0,1},
    // experts 8le+2p, 8le+2p+1 (perm maps back exactly to this)
    float* gl = g_logits[kh];
#pragma unroll
    for (int j = 0; j < 2; j++) {
        int t = tok0 + warp * 8 + lt * 2 + j;
#pragma unroll
        for (int p = 0; p < 4; p++) {
            union { unsigned long long u; float2 f; } cv; cv.u = sum[j][p];
            *(float2*)(gl + (size_t)t * NE + 8 * le + 2 * p) = cv.f;
        }
    }
}

// ---------------- C: epilogue (unchanged from R8 — idx-exact) ----------------
__global__ __launch_bounds__(THREADS) void epi_kernel(
    float* __restrict__ out, int T, int S)
{
    __shared__ float score_acc[NE];
    __shared__ int   cnt_acc[NE];
    __shared__ unsigned is_last;
    __shared__ float part[4];

    const int tid  = threadIdx.x;
    const int lane = tid & 31;
    const int warp = tid >> 5;
    const int lt   = lane >> 3;
    const int le   = lane & 7;
    const int bid  = blockIdx.x;
    const int tok0 = bid * EPB;

    if (tid < NE) { score_acc[tid] = 0.0f; cnt_acc[tid] = 0; }
    __syncthreads();

    for (int j = 0; j < 4; j++) {
        const int t = tok0 + warp * 16 + lt * 4 + j;
        float4 a0 = *(const float4*)(g_logits[0] + (size_t)t * NE + 8 * le);
        float4 a1 = *(const float4*)(g_logits[0] + (size_t)t * NE + 8 * le + 4);
        float4 b0 = *(const float4*)(g_logits[1] + (size_t)t * NE + 8 * le);
        float4 b1 = *(const float4*)(g_logits[1] + (size_t)t * NE + 8 * le + 4);
        float v[8];
        v[0]=a0.x+b0.x; v[1]=a0.y+b0.y; v[2]=a0.z+b0.z; v[3]=a0.w+b0.w;
        v[4]=a1.x+b1.x; v[5]=a1.y+b1.y; v[6]=a1.z+b1.z; v[7]=a1.w+b1.w;

        float m = v[0];
#pragma unroll
        for (int i = 1; i < 8; i++) m = fmaxf(m, v[i]);
#pragma unroll
        for (int off = 1; off < 8; off <<= 1)
            m = fmaxf(m, __shfl_xor_sync(0xffffffffu, m, off));

        float s[8], z = 0.0f;
#pragma unroll
        for (int i = 0; i < 8; i++) { s[i] = __expf(v[i] - m); z += s[i]; }
#pragma unroll
        for (int off = 1; off < 8; off <<= 1)
            z += __shfl_xor_sync(0xffffffffu, z, off);
        float inv = 1.0f / z;
#pragma unroll
        for (int i = 0; i < 8; i++) {
            s[i] *= inv;
            atomicAdd(&score_acc[8 * le + i], s[i]);
        }

        unsigned used = 0;
        float wsum = 0.0f;
        float outw[KTOP]; int outi[KTOP];
#pragma unroll
        for (int it = 0; it < KTOP; it++) {
            float bv = -3.4e38f; int bi = 127;
#pragma unroll
            for (int i = 0; i < 8; i++) {
                bool ok = !((used >> i) & 1u) && (v[i] > bv);
                bv = ok ? v[i] : bv;
                bi = ok ? (8 * le + i) : bi;
            }
#pragma unroll
            for (int off = 1; off < 8; off <<= 1) {
                float ov = __shfl_xor_sync(0xffffffffu, bv, off);
                int   oi = __shfl_xor_sync(0xffffffffu, bi, off);
                if (ov > bv || (ov == bv && oi < bi)) { bv = ov; bi = oi; }
            }
            int ii = bi & 7;
            float cand = s[0];
#pragma unroll
            for (int i = 1; i < 8; i++) cand = (ii == i) ? s[i] : cand;
            float sc = __shfl_sync(0xffffffffu, cand, (lane & 24) | (bi >> 3));
            wsum += sc;
            outw[it] = sc; outi[it] = bi;
            if ((bi >> 3) == le) used |= 1u << (bi & 7);
            if (le == 0) atomicAdd(&cnt_acc[bi], 1);
        }
        if (le == 0) {
            float invw = 1.0f / (wsum + 1e-20f);
#pragma unroll
            for (int it = 0; it < KTOP; it++) {
                out[(size_t)t * KTOP + it] = (float)outi[it];
                out[(size_t)T * KTOP + (size_t)t * KTOP + it] = outw[it] * invw;
            }
        }
    }
    __syncthreads();

    if (tid < NE) {
        g_pscore[bid * NE + tid] = score_acc[tid];
        g_pcnt[bid * NE + tid]   = cnt_acc[tid];
    }
    __threadfence();
    __syncthreads();
    if (tid == 0) {
        unsigned tkt = atomicAdd(&g_ticket, 1u);
        is_last = (tkt == (unsigned)(gridDim.x - 1));
    }
    __syncthreads();

    if (is_last) {
        if (tid == 0) g_ticket = 0;
        __threadfence();
        float local = 0.0f;
        for (int p = tid; p < NB * NE; p += THREADS) {
            int b = p >> 6, e = p & 63;
            float sc = 0.0f; int cn = 0;
            const int base = b * BPB;
            for (int blk = 0; blk < BPB; blk++) {
                sc += g_pscore[(base + blk) * NE + e];
                cn += g_pcnt[(base + blk) * NE + e];
            }
            float ce = (float)cn * ((float)NE / ((float)S * (float)KTOP));
            local += ce * (sc / (float)S);
        }
#pragma unroll
        for (int off = 16; off; off >>= 1)
            local += __shfl_xor_sync(0xffffffffu, local, off);
        if (lane == 0) part[warp] = local;
        __syncthreads();
        if (tid == 0) {
            float sm = part[0] + part[1] + part[2] + part[3];
            out[(size_t)2 * T * KTOP] = (sm / (float)NB) * 1e-3f;
        }
    }
}

extern "C" void kernel_launch(void* const* d_in, const int* in_sizes, int n_in,
                              void* d_out, int out_size) {
    const float* x = (const float*)d_in[0];
    const float* w = (const float*)d_in[1];
    float* out = (float*)d_out;
    int h = in_sizes[1] / NE;     // 2048
    int T = in_sizes[0] / h;      // 16384
    int S = T / NB;               // 4096

    transpose_kernel<<<h / 16, 256>>>(w, h);
    gemm_kernel<<<(T / TPB) * 2, THREADS>>>(x, h);
    epi_kernel<<<T / EPB, THREADS>>>(out, T, S);
}

// round 10
// speedup vs baseline: 2.2838x; 1.2843x over previous
#include <cuda_runtime.h>
#include <cstddef>
#include <cstdint>

// MoEGate, 3-phase: (A) W transpose+permute -> wT[k][perm(e)],
// (B) split-K GEMM, f32x2 expert-pair packing -> fp32 partial logits,
// (C) epilogue (merge halves, softmax, top-6 + renorm, seq-aux loss).
// x: [T=16384, h=2048] f32, W: [E=64, h] f32.
// Output (f32): [topk_idx (T*6) | topk_weight (T*6) | aux_loss (1)]
//
// R10 = R8's 4tok x 4pair tile (12 LDS.128 per 64 FFMA2 -> crossbar wall
// ~90us, vs R9's 40/32 ratio = 150us wall, measured) WITHOUT the register
// cap that made R8 spill, plus R9's permuted wT (single-128B w loads).
// Summation structure bit-identical to R8/R9 (idx-exact vs jax):
// sequential k within 32-chunks, add2 chunk merge, split-K=2.

#define NE 64
#define KTOP 6
#define NB 4
#define MAXT 16384
#define MAXH 2048
#define TPB 64                // tokens per GEMM block
#define THREADS 128           // 4 warps; lane = lt*8 + le
#define CHUNK 32              // k per stage
#define XPITCH 36             // floats per staged x row
#define EPB 64                // epilogue tokens per block
#define NBLK_C 256            // epilogue blocks = T/EPB
#define BPB 64                // epilogue blocks per batch

__device__ float    g_wt[MAXH * NE];             // wT[k][perm(e)], 512KB
__device__ float    g_logits[2][MAXT * NE];      // split-K partials, 8MB
__device__ float    g_pscore[NBLK_C * NE];
__device__ int      g_pcnt[NBLK_C * NE];
__device__ unsigned g_ticket;                    // self-resetting

static __device__ __forceinline__ void ffma2(unsigned long long& d,
                                             unsigned long long a,
                                             unsigned long long b) {
    asm("fma.rn.f32x2 %0, %1, %2, %0;" : "+l"(d) : "l"(a), "l"(b));
}
static __device__ __forceinline__ void add2(unsigned long long& d,
                                            unsigned long long a) {
    asm("add.rn.f32x2 %0, %0, %1;" : "+l"(d) : "l"(a));
}
static __device__ __forceinline__ unsigned long long dup2(float f) {
    unsigned long long r;
    asm("mov.b64 %0, {%1, %1};" : "=l"(r) : "f"(f));
    return r;
}
static __device__ __forceinline__ void cpa16(uint32_t dst, const void* src) {
    asm volatile("cp.async.cg.shared.global [%0], [%1], 16;"
                 :: "r"(dst), "l"(src));
}

// ---------------- A: transpose W[e][k] -> wT[k][perm(e)] ----------------
// perm(e): e = 8*le + i  ->  (i&4)*8 + le*4 + (i&3)
// lanes' wlo (experts 8le..8le+3) sit at bytes [le*16, le*16+16) of the
// first 128B half of each wT row; whi in the second half.
__global__ void transpose_kernel(const float* __restrict__ w, int h) {
    __shared__ float s[16 * 65];
    const int k0 = blockIdx.x * 16;
    for (int idx = threadIdx.x; idx < 16 * 64; idx += 256) {
        int e = idx >> 4, kk = idx & 15;
        s[kk * 65 + e] = w[(size_t)e * h + k0 + kk];
    }
    __syncthreads();
    for (int idx = threadIdx.x; idx < 16 * 64; idx += 256) {
        int kk = idx >> 6, e = idx & 63;
        int le = e >> 3, i = e & 7;
        int pos = ((i & 4) << 3) + le * 4 + (i & 3);
        g_wt[(size_t)(k0 + kk) * NE + pos] = s[kk * 65 + e];
    }
}

// ---------------- B: split-K GEMM -> partial logits ----------------
__global__ __launch_bounds__(THREADS) void gemm_kernel(
    const float* __restrict__ x, int h)
{
    __shared__ __align__(16) float xs[2][TPB * XPITCH];   // 18KB
    __shared__ __align__(16) float wts[2][CHUNK * NE];    // 16KB

    const int tid  = threadIdx.x;
    const int lane = tid & 31;
    const int warp = tid >> 5;
    const int lt   = lane >> 3;       // token group 0..3
    const int le   = lane & 7;        // expert group 0..7
    const int tile = blockIdx.x >> 1;
    const int kh   = blockIdx.x & 1;  // k-half
    const int tok0 = tile * TPB;
    const int kbase = kh * (h >> 1);
    const int nchunk = (h >> 1) / CHUNK;   // 32

    unsigned long long acc[4][4], sum[4][4];
#pragma unroll
    for (int j = 0; j < 4; j++)
#pragma unroll
        for (int p = 0; p < 4; p++) { acc[j][p] = 0ull; sum[j][p] = 0ull; }

    // stage: x 64 rows x 8 quads (512) + wT 32 rows x 16 quads (512)
    auto stage = [&](int c, int buf) {
        const int k0 = kbase + c * CHUNK;
#pragma unroll
        for (int j = 0; j < 8; j++) {
            int cj = tid + j * THREADS;
            if (cj < 512) {
                int row = cj >> 3, q = cj & 7;
                cpa16((uint32_t)__cvta_generic_to_shared(
                          &xs[buf][row * XPITCH + q * 4]),
                      x + (size_t)(tok0 + row) * h + k0 + q * 4);
            } else {
                int c2 = cj - 512;
                int k = c2 >> 4, q = c2 & 15;
                cpa16((uint32_t)__cvta_generic_to_shared(
                          &wts[buf][k * NE + q * 4]),
                      g_wt + (size_t)(k0 + k) * NE + q * 4);
            }
        }
    };

    stage(0, 0);
    asm volatile("cp.async.commit_group;" ::: "memory");

    for (int c = 0; c < nchunk; c++) {
        const int buf = c & 1;
        asm volatile("cp.async.wait_group 0;" ::: "memory");
        __syncthreads();
        if (c + 1 < nchunk) {
            stage(c + 1, buf ^ 1);
            asm volatile("cp.async.commit_group;" ::: "memory");
        }

        const float* xb = &xs[buf][(warp * 16 + lt * 4) * XPITCH];
        const float* wb = &wts[buf][le * 4];   // wlo at +0, whi at +32
#pragma unroll
        for (int kk = 0; kk < CHUNK; kk += 4) {
            float4 xv0 = *(const float4*)(xb + 0 * XPITCH + kk);
            float4 xv1 = *(const float4*)(xb + 1 * XPITCH + kk);
            float4 xv2 = *(const float4*)(xb + 2 * XPITCH + kk);
            float4 xv3 = *(const float4*)(xb + 3 * XPITCH + kk);
#pragma unroll
            for (int k2 = 0; k2 < 4; k2++) {
                ulonglong2 wlo = *(const ulonglong2*)(wb + (kk + k2) * NE);
                ulonglong2 whi = *(const ulonglong2*)(wb + (kk + k2) * NE + 32);
                unsigned long long d0 = dup2(((const float*)&xv0)[k2]);
                unsigned long long d1 = dup2(((const float*)&xv1)[k2]);
                unsigned long long d2 = dup2(((const float*)&xv2)[k2]);
                unsigned long long d3 = dup2(((const float*)&xv3)[k2]);
                ffma2(acc[0][0], d0, wlo.x); ffma2(acc[0][1], d0, wlo.y);
                ffma2(acc[0][2], d0, whi.x); ffma2(acc[0][3], d0, whi.y);
                ffma2(acc[1][0], d1, wlo.x); ffma2(acc[1][1], d1, wlo.y);
                ffma2(acc[1][2], d1, whi.x); ffma2(acc[1][3], d1, whi.y);
                ffma2(acc[2][0], d2, wlo.x); ffma2(acc[2][1], d2, wlo.y);
                ffma2(acc[2][2], d2, whi.x); ffma2(acc[2][3], d2, whi.y);
                ffma2(acc[3][0], d3, wlo.x); ffma2(acc[3][1], d3, wlo.y);
                ffma2(acc[3][2], d3, whi.x); ffma2(acc[3][3], d3, whi.y);
            }
        }
        // merge 32-term chunk partials (identical structure -> same bits)
#pragma unroll
        for (int j = 0; j < 4; j++)
#pragma unroll
            for (int p = 0; p < 4; p++) { add2(sum[j][p], acc[j][p]); acc[j][p] = 0ull; }
    }

    // store partial logits [t][e]: lane -> tokens warp*16+lt*4+{0..3},
    // experts 8le+2p, 8le+2p+1
    float* gl = g_logits[kh];
#pragma unroll
    for (int j = 0; j < 4; j++) {
        int t = tok0 + warp * 16 + lt * 4 + j;
#pragma unroll
        for (int p = 0; p < 4; p++) {
            union { unsigned long long u; float2 f; } cv; cv.u = sum[j][p];
            *(float2*)(gl + (size_t)t * NE + 8 * le + 2 * p) = cv.f;
        }
    }
}

// ---------------- C: epilogue (unchanged — idx-exact) ----------------
__global__ __launch_bounds__(THREADS) void epi_kernel(
    float* __restrict__ out, int T, int S)
{
    __shared__ float score_acc[NE];
    __shared__ int   cnt_acc[NE];
    __shared__ unsigned is_last;
    __shared__ float part[4];

    const int tid  = threadIdx.x;
    const int lane = tid & 31;
    const int warp = tid >> 5;
    const int lt   = lane >> 3;
    const int le   = lane & 7;
    const int bid  = blockIdx.x;
    const int tok0 = bid * EPB;

    if (tid < NE) { score_acc[tid] = 0.0f; cnt_acc[tid] = 0; }
    __syncthreads();

    for (int j = 0; j < 4; j++) {
        const int t = tok0 + warp * 16 + lt * 4 + j;
        float4 a0 = *(const float4*)(g_logits[0] + (size_t)t * NE + 8 * le);
        float4 a1 = *(const float4*)(g_logits[0] + (size_t)t * NE + 8 * le + 4);
        float4 b0 = *(const float4*)(g_logits[1] + (size_t)t * NE + 8 * le);
        float4 b1 = *(const float4*)(g_logits[1] + (size_t)t * NE + 8 * le + 4);
        float v[8];
        v[0]=a0.x+b0.x; v[1]=a0.y+b0.y; v[2]=a0.z+b0.z; v[3]=a0.w+b0.w;
        v[4]=a1.x+b1.x; v[5]=a1.y+b1.y; v[6]=a1.z+b1.z; v[7]=a1.w+b1.w;

        float m = v[0];
#pragma unroll
        for (int i = 1; i < 8; i++) m = fmaxf(m, v[i]);
#pragma unroll
        for (int off = 1; off < 8; off <<= 1)
            m = fmaxf(m, __shfl_xor_sync(0xffffffffu, m, off));

        float s[8], z = 0.0f;
#pragma unroll
        for (int i = 0; i < 8; i++) { s[i] = __expf(v[i] - m); z += s[i]; }
#pragma unroll
        for (int off = 1; off < 8; off <<= 1)
            z += __shfl_xor_sync(0xffffffffu, z, off);
        float inv = 1.0f / z;
#pragma unroll
        for (int i = 0; i < 8; i++) {
            s[i] *= inv;
            atomicAdd(&score_acc[8 * le + i], s[i]);
        }

        unsigned used = 0;
        float wsum = 0.0f;
        float outw[KTOP]; int outi[KTOP];
#pragma unroll
        for (int it = 0; it < KTOP; it++) {
            float bv = -3.4e38f; int bi = 127;
#pragma unroll
            for (int i = 0; i < 8; i++) {
                bool ok = !((used >> i) & 1u) && (v[i] > bv);
                bv = ok ? v[i] : bv;
                bi = ok ? (8 * le + i) : bi;
            }
#pragma unroll
            for (int off = 1; off < 8; off <<= 1) {
                float ov = __shfl_xor_sync(0xffffffffu, bv, off);
                int   oi = __shfl_xor_sync(0xffffffffu, bi, off);
                if (ov > bv || (ov == bv && oi < bi)) { bv = ov; bi = oi; }
            }
            int ii = bi & 7;
            float cand = s[0];
#pragma unroll
            for (int i = 1; i < 8; i++) cand = (ii == i) ? s[i] : cand;
            float sc = __shfl_sync(0xffffffffu, cand, (lane & 24) | (bi >> 3));
            wsum += sc;
            outw[it] = sc; outi[it] = bi;
            if ((bi >> 3) == le) used |= 1u << (bi & 7);
            if (le == 0) atomicAdd(&cnt_acc[bi], 1);
        }
        if (le == 0) {
            float invw = 1.0f / (wsum + 1e-20f);
#pragma unroll
            for (int it = 0; it < KTOP; it++) {
                out[(size_t)t * KTOP + it] = (float)outi[it];
                out[(size_t)T * KTOP + (size_t)t * KTOP + it] = outw[it] * invw;
            }
        }
    }
    __syncthreads();

    if (tid < NE) {
        g_pscore[bid * NE + tid] = score_acc[tid];
        g_pcnt[bid * NE + tid]   = cnt_acc[tid];
    }
    __threadfence();
    __syncthreads();
    if (tid == 0) {
        unsigned tkt = atomicAdd(&g_ticket, 1u);
        is_last = (tkt == (unsigned)(gridDim.x - 1));
    }
    __syncthreads();

    if (is_last) {
        if (tid == 0) g_ticket = 0;
        __threadfence();
        float local = 0.0f;
        for (int p = tid; p < NB * NE; p += THREADS) {
            int b = p >> 6, e = p & 63;
            float sc = 0.0f; int cn = 0;
            const int base = b * BPB;
            for (int blk = 0; blk < BPB; blk++) {
                sc += g_pscore[(base + blk) * NE + e];
                cn += g_pcnt[(base + blk) * NE + e];
            }
            float ce = (float)cn * ((float)NE / ((float)S * (float)KTOP));
            local += ce * (sc / (float)S);
        }
#pragma unroll
        for (int off = 16; off; off >>= 1)
            local += __shfl_xor_sync(0xffffffffu, local, off);
        if (lane == 0) part[warp] = local;
        __syncthreads();
        if (tid == 0) {
            float sm = part[0] + part[1] + part[2] + part[3];
            out[(size_t)2 * T * KTOP] = (sm / (float)NB) * 1e-3f;
        }
    }
}

extern "C" void kernel_launch(void* const* d_in, const int* in_sizes, int n_in,
                              void* d_out, int out_size) {
    const float* x = (const float*)d_in[0];
    const float* w = (const float*)d_in[1];
    float* out = (float*)d_out;
    int h = in_sizes[1] / NE;     // 2048
    int T = in_sizes[0] / h;      // 16384
    int S = T / NB;               // 4096

    transpose_kernel<<<h / 16, 256>>>(w, h);
    gemm_kernel<<<(T / TPB) * 2, THREADS>>>(x, h);
    epi_kernel<<<T / EPB, THREADS>>>(out, T, S);
}